// round 11
// baseline (speedup 1.0000x reference)
#include <cuda_runtime.h>
#include <math.h>

// Problem constants
#define NN 10000     // nodes
#define TT 6         // timesteps
#define FF 64        // input features
#define HH 64        // HID
#define NH 4         // heads
#define EE 160000    // raw edges
#define EP 170000    // edges + self loops
#define G1 256       // HEADS*HID (layer1 xw width)

// ---------------- device scratch (no allocation allowed) ----------------
__device__ int   g_is64;
__device__ int   g_src[EP], g_dst[EP];
__device__ float g_xw0[NN*HH];
__device__ float g_ssrc0[NN*NH], g_sdst0[NN*NH], g_ssum0[NN*NH];
__device__ float g_acc0[NN*HH];
__device__ float g_h[NN*HH];          // layer0 output (after elu)
__device__ float g_xw1[NN*G1];
__device__ float g_ssrc1[NN*NH], g_sdst1[NN*NH], g_ssum1[NN*NH];
__device__ float g_acc1[NN*G1];
__device__ float g_Ht[NN*HH];         // per-timestep GAT output (after LN)
__device__ float g_hgru[NN*HH];       // GRU hidden state
__device__ float g_gi[NN*192], g_gh[NN*192];

// ---------------- dtype autodetect for edge_index ----------------
// If edge_index is int64 (little-endian, values < 2^31), every odd 32-bit word
// of the buffer is 0. If it is int32, odd words are independent node ids and
// are almost surely not all zero over 2048 samples.
__global__ void k_detect(const int* __restrict__ ei32) {
    __shared__ int acc;
    if (threadIdx.x == 0) acc = 0;
    __syncthreads();
    int bad = 0;
    for (int i = 1 + 2*threadIdx.x; i < 4096; i += 512)
        bad |= ei32[i];
    if (bad) atomicOr(&acc, 1);
    __syncthreads();
    if (threadIdx.x == 0) g_is64 = (acc == 0) ? 1 : 0;
}

// ---------------- prep: edge arrays + edge-index output ----------------
__global__ void k_prep(const void* __restrict__ eiv, float* __restrict__ out_idx) {
    int i = blockIdx.x * blockDim.x + threadIdx.x;
    if (i >= EP) return;
    int s, d;
    if (i < EE) {
        if (g_is64) {
            const long long* ei = (const long long*)eiv;
            s = (int)ei[i]; d = (int)ei[EE + i];
        } else {
            const int* ei = (const int*)eiv;
            s = ei[i]; d = ei[EE + i];
        }
    } else {
        s = i - EE; d = i - EE;
    }
    // crash insurance: clamp into valid range
    s = s < 0 ? 0 : (s >= NN ? NN - 1 : s);
    d = d < 0 ? 0 : (d >= NN ? NN - 1 : d);
    g_src[i] = s; g_dst[i] = d;
    out_idx[i]      = (float)s;
    out_idx[EP + i] = (float)d;
}

__global__ void k_init_h() {
    int i = blockIdx.x * blockDim.x + threadIdx.x;
    int stride = gridDim.x * blockDim.x;
    for (int j = i; j < NN*HH; j += stride) g_hgru[j] = 0.0f;
}

// ---------------- per-timestep zeroing of accumulators ----------------
__global__ void k_zero() {
    int i = blockIdx.x * blockDim.x + threadIdx.x;
    int stride = gridDim.x * blockDim.x;
    for (int j = i; j < NN*G1; j += stride) g_acc1[j] = 0.0f;
    for (int j = i; j < NN*HH; j += stride) g_acc0[j] = 0.0f;
    for (int j = i; j < NN*NH; j += stride) { g_ssum0[j] = 0.0f; g_ssum1[j] = 0.0f; }
}

// ---------------- layer0 GEMM: xw0 = x[:,t,:] @ W0, fused a-reductions ----------------
// block = 256 threads = 4 groups of 64; group handles one node per iter; thread owns col j
__global__ void __launch_bounds__(256) k_gemm0(
    const float* __restrict__ x, const float* __restrict__ W0,
    const float* __restrict__ a_src0, const float* __restrict__ a_dst0, int t)
{
    int j = threadIdx.x & 63;
    int g = threadIdx.x >> 6;
    float wcol[FF];
    #pragma unroll
    for (int k = 0; k < FF; k++) wcol[k] = W0[k*HH + j];
    float asv = a_src0[j];   // [4,16] flattened == j
    float adv = a_dst0[j];
    int h = j >> 4;
    for (int n = blockIdx.x*4 + g; n < NN; n += gridDim.x*4) {
        const float* xr = x + (size_t)n*TT*FF + (size_t)t*FF;
        float acc = 0.0f;
        #pragma unroll
        for (int k = 0; k < FF; k++) acc += xr[k] * wcol[k];
        g_xw0[n*HH + j] = acc;
        float ps = acc * asv, pd = acc * adv;
        #pragma unroll
        for (int off = 8; off > 0; off >>= 1) {
            ps += __shfl_down_sync(0xffffffffu, ps, off, 16);
            pd += __shfl_down_sync(0xffffffffu, pd, off, 16);
        }
        if ((j & 15) == 0) {
            g_ssrc0[n*NH + h] = ps;
            g_sdst0[n*NH + h] = pd;
        }
    }
}

// ---------------- layer0 edge scatter (unnormalized softmax-weighted sum) ----------------
// block = 256 threads = 4 edges x 64 channels
__global__ void __launch_bounds__(256) k_edge0() {
    int e = blockIdx.x*4 + (threadIdx.x >> 6);
    if (e >= EP) return;
    int j = threadIdx.x & 63;
    int s = g_src[e], d = g_dst[e];
    int h = j >> 4;
    float al = g_ssrc0[s*NH + h] + g_sdst0[d*NH + h];
    al = al > 0.0f ? al : 0.2f*al;
    float ex = __expf(al);
    if ((j & 15) == 0) atomicAdd(&g_ssum0[d*NH + h], ex);
    atomicAdd(&g_acc0[d*HH + j], ex * g_xw0[s*HH + j]);
}

// ---------------- layer0 node epilogue: normalize + bias + elu ----------------
__global__ void k_node0(const float* __restrict__ b0) {
    int i = blockIdx.x * blockDim.x + threadIdx.x;
    if (i >= NN*HH) return;
    int n = i >> 6, j = i & 63, h = j >> 4;
    float v = g_acc0[i] / (g_ssum0[n*NH + h] + 1e-16f) + b0[j];
    g_h[i] = v > 0.0f ? v : (expf(v) - 1.0f);
}

// ---------------- layer1 GEMM: xw1 = h @ W1 [64,256], fused a-reductions ----------------
// block = 256 threads, one node per iter, thread owns col j (register W column)
__global__ void __launch_bounds__(256) k_gemm1(
    const float* __restrict__ W1,
    const float* __restrict__ a_src1, const float* __restrict__ a_dst1)
{
    int j = threadIdx.x;
    float wcol[HH];
    #pragma unroll
    for (int k = 0; k < HH; k++) wcol[k] = W1[k*G1 + j];
    float asv = a_src1[j];   // [4,64] flattened == j
    float adv = a_dst1[j];
    __shared__ float sh_h[HH];
    __shared__ float sred[16];
    int warp = j >> 5, lane = j & 31;
    for (int n = blockIdx.x; n < NN; n += gridDim.x) {
        if (j < HH) sh_h[j] = g_h[n*HH + j];
        __syncthreads();
        float acc = 0.0f;
        #pragma unroll
        for (int k = 0; k < HH; k++) acc += sh_h[k] * wcol[k];
        g_xw1[n*G1 + j] = acc;
        float ps = acc * asv, pd = acc * adv;
        #pragma unroll
        for (int off = 16; off > 0; off >>= 1) {
            ps += __shfl_down_sync(0xffffffffu, ps, off);
            pd += __shfl_down_sync(0xffffffffu, pd, off);
        }
        if (lane == 0) { sred[warp] = ps; sred[8 + warp] = pd; }
        __syncthreads();
        if (j < NH) {
            g_ssrc1[n*NH + j] = sred[2*j] + sred[2*j + 1];
            g_sdst1[n*NH + j] = sred[8 + 2*j] + sred[8 + 2*j + 1];
        }
        __syncthreads();
    }
}

// ---------------- layer1 edge scatter ----------------
// block = 256 threads = 1 edge x 256 channels
__global__ void __launch_bounds__(256) k_edge1() {
    int e = blockIdx.x;
    int j = threadIdx.x;
    int s = g_src[e], d = g_dst[e];
    int h = j >> 6;
    float al = g_ssrc1[s*NH + h] + g_sdst1[d*NH + h];
    al = al > 0.0f ? al : 0.2f*al;
    float ex = __expf(al);
    if ((j & 63) == 0) atomicAdd(&g_ssum1[d*NH + h], ex);
    atomicAdd(&g_acc1[d*G1 + j], ex * g_xw1[s*G1 + j]);
}

// ---------------- layer1 node epilogue: normalize + head-mean + bias + elu + LayerNorm ----------------
// block = 256 = 4 nodes x 64 channels (N divisible by 4)
__global__ void __launch_bounds__(256) k_node1(
    const float* __restrict__ b1, const float* __restrict__ ln_g, const float* __restrict__ ln_b)
{
    int n = blockIdx.x*4 + (threadIdx.x >> 6);
    int c = threadIdx.x & 63;
    int g = threadIdx.x >> 6;
    int wing = (threadIdx.x >> 5) & 1;
    int lane = threadIdx.x & 31;
    __shared__ float ps[4][2], qs[4][2];

    float sum4 = 0.0f;
    #pragma unroll
    for (int h = 0; h < 4; h++)
        sum4 += g_acc1[n*G1 + h*HH + c] / (g_ssum1[n*NH + h] + 1e-16f);
    float v = sum4 * 0.25f + b1[c];
    v = v > 0.0f ? v : (expf(v) - 1.0f);

    float s1 = v, s2 = v*v;
    #pragma unroll
    for (int off = 16; off > 0; off >>= 1) {
        s1 += __shfl_down_sync(0xffffffffu, s1, off);
        s2 += __shfl_down_sync(0xffffffffu, s2, off);
    }
    if (lane == 0) { ps[g][wing] = s1; qs[g][wing] = s2; }
    __syncthreads();
    float mu  = (ps[g][0] + ps[g][1]) * (1.0f/64.0f);
    float var = (qs[g][0] + qs[g][1]) * (1.0f/64.0f) - mu*mu;
    float o = (v - mu) * rsqrtf(var + 1e-5f) * ln_g[c] + ln_b[c];
    g_Ht[n*HH + c] = o;
}

// ---------------- GRU GEMV: out[n,j] = dot(in[n,:], W[j,:]) + b[j] ----------------
// which==0: in=g_Ht  -> g_gi ;  which==1: in=g_hgru -> g_gh
__global__ void __launch_bounds__(192) k_gemv(
    const float* __restrict__ W, const float* __restrict__ b, int which)
{
    int j = threadIdx.x;  // 0..191
    float wrow[HH];
    #pragma unroll
    for (int k = 0; k < HH; k++) wrow[k] = W[j*HH + k];
    float bj = b[j];
    const float* inbuf = (which == 0) ? g_Ht : g_hgru;
    float* outbuf = (which == 0) ? g_gi : g_gh;
    __shared__ float sh[HH];
    for (int n = blockIdx.x; n < NN; n += gridDim.x) {
        if (j < HH) sh[j] = inbuf[n*HH + j];
        __syncthreads();
        float acc = bj;
        #pragma unroll
        for (int k = 0; k < HH; k++) acc += sh[k] * wrow[k];
        outbuf[n*192 + j] = acc;
        __syncthreads();
    }
}

// ---------------- GRU combine ----------------
__global__ void k_gru() {
    int i = blockIdx.x * blockDim.x + threadIdx.x;
    if (i >= NN*HH) return;
    int n = i >> 6, c = i & 63;
    float ir = g_gi[n*192 + c],      hr = g_gh[n*192 + c];
    float iz = g_gi[n*192 + 64 + c], hz = g_gh[n*192 + 64 + c];
    float ig = g_gi[n*192 + 128 + c], hg = g_gh[n*192 + 128 + c];
    float r = 1.0f / (1.0f + expf(-(ir + hr)));
    float z = 1.0f / (1.0f + expf(-(iz + hz)));
    float gg = tanhf(ig + r*hg);
    float h = g_hgru[i];
    g_hgru[i] = (1.0f - z)*gg + z*h;
}

// ---------------- alpha output (last timestep's attention, layer1) ----------------
__global__ void k_alpha(float* __restrict__ out_alpha) {
    int i = blockIdx.x * blockDim.x + threadIdx.x;
    if (i >= EP*NH) return;
    int e = i >> 2, h = i & 3;
    int s = g_src[e], d = g_dst[e];
    float al = g_ssrc1[s*NH + h] + g_sdst1[d*NH + h];
    al = al > 0.0f ? al : 0.2f*al;
    float ex = __expf(al);
    out_alpha[i] = ex / (g_ssum1[d*NH + h] + 1e-16f);
}

// ---------------- final hT copy ----------------
__global__ void k_copy_h(float* __restrict__ out_h) {
    int i = blockIdx.x * blockDim.x + threadIdx.x;
    if (i < NN*HH) out_h[i] = g_hgru[i];
}

// ---------------- launch ----------------
extern "C" void kernel_launch(void* const* d_in, const int* in_sizes, int n_in,
                              void* d_out, int out_size) {
    const float* x       = (const float*)d_in[0];
    const void*  ei      = d_in[1];              // int32 or int64, autodetected
    const float* W0      = (const float*)d_in[2];
    const float* a_src0  = (const float*)d_in[3];
    const float* a_dst0  = (const float*)d_in[4];
    const float* b0      = (const float*)d_in[5];
    const float* W1      = (const float*)d_in[6];
    const float* a_src1  = (const float*)d_in[7];
    const float* a_dst1  = (const float*)d_in[8];
    const float* b1      = (const float*)d_in[9];
    const float* ln_g    = (const float*)d_in[10];
    const float* ln_b    = (const float*)d_in[11];
    const float* W_ih    = (const float*)d_in[12];
    const float* W_hh    = (const float*)d_in[13];
    const float* b_ih    = (const float*)d_in[14];
    const float* b_hh    = (const float*)d_in[15];

    float* out       = (float*)d_out;
    float* out_h     = out;                        // [N*HID]
    float* out_alpha = out + NN*HH;                // [EP*NH]
    float* out_idx   = out + NN*HH + EP*NH;        // [2*EP]

    k_detect<<<1, 256>>>((const int*)ei);
    k_prep<<<(EP + 255)/256, 256>>>(ei, out_idx);
    k_init_h<<<1024, 256>>>();

    for (int t = 0; t < TT; t++) {
        k_zero<<<2048, 256>>>();
        k_gemm0<<<625, 256>>>(x, W0, a_src0, a_dst0, t);
        k_edge0<<<(EP + 3)/4, 256>>>();
        k_node0<<<(NN*HH + 255)/256, 256>>>(b0);
        k_gemm1<<<592, 256>>>(W1, a_src1, a_dst1);
        k_edge1<<<EP, 256>>>();
        k_node1<<<NN/4, 256>>>(b1, ln_g, ln_b);
        k_gemv<<<512, 192>>>(W_ih, b_ih, 0);
        k_gemv<<<512, 192>>>(W_hh, b_hh, 1);
        k_gru<<<(NN*HH + 255)/256, 256>>>();
    }

    k_alpha<<<(EP*NH + 255)/256, 256>>>(out_alpha);
    k_copy_h<<<(NN*HH + 255)/256, 256>>>(out_h);
}

// round 16
// speedup vs baseline: 1.6299x; 1.6299x over previous
#include <cuda_runtime.h>
#include <math.h>

// Problem constants
#define NN 10000     // nodes
#define TT 6         // timesteps
#define FF 64        // input features
#define HH 64        // HID
#define NH 4         // heads
#define EE 160000    // raw edges
#define EP 170000    // edges + self loops
#define G1 256       // HEADS*HID (layer1 xw width)

// ---------------- device scratch (no allocation allowed) ----------------
__device__ int   g_is64;
__device__ int   g_src[EP], g_dst[EP];
__device__ int   g_deg[NN], g_off[NN+1], g_cur[NN];
__device__ int   g_ce[EP];                       // edge ids grouped by dst (CSR)

__device__ float g_xw0[TT*NN*HH];                // [t][n][64]
__device__ float g_ssrc0[TT*NN*NH], g_sdst0[TT*NN*NH];
__device__ float g_ex0[TT*EP*NH];                // [t][e][4]
__device__ float g_h[TT*NN*HH];                  // layer0 output (after elu)
__device__ float g_xw1[TT*NN*G1];                // [t][n][256]
__device__ float g_ssrc1[TT*NN*NH], g_sdst1[TT*NN*NH];
__device__ float g_ex1[TT*EP*NH];
__device__ float g_ssum1[NN*NH];                 // last-timestep softmax sums (for alpha)
__device__ float g_Ht[TT*NN*HH];                 // per-timestep GAT output (after LN)
__device__ float g_hgru[NN*HH];                  // GRU hidden state

// ---------------- dtype autodetect for edge_index ----------------
__global__ void k_detect(const int* __restrict__ ei32) {
    __shared__ int acc;
    if (threadIdx.x == 0) acc = 0;
    __syncthreads();
    int bad = 0;
    for (int i = 1 + 2*threadIdx.x; i < 4096; i += 512) bad |= ei32[i];
    if (bad) atomicOr(&acc, 1);
    __syncthreads();
    if (threadIdx.x == 0) g_is64 = (acc == 0) ? 1 : 0;
}

__global__ void k_zerodeg() {
    int i = blockIdx.x * blockDim.x + threadIdx.x;
    if (i < NN) g_deg[i] = 0;
    if (i < NN*HH) g_hgru[i] = 0.0f;
}

// ---------------- prep: parse edges, histogram degrees, emit edge-index output ----
__global__ void k_prep(const void* __restrict__ eiv, float* __restrict__ out_idx) {
    int i = blockIdx.x * blockDim.x + threadIdx.x;
    if (i >= EP) return;
    int s, d;
    if (i < EE) {
        if (g_is64) {
            const long long* ei = (const long long*)eiv;
            s = (int)ei[i]; d = (int)ei[EE + i];
        } else {
            const int* ei = (const int*)eiv;
            s = ei[i]; d = ei[EE + i];
        }
    } else { s = i - EE; d = i - EE; }
    s = s < 0 ? 0 : (s >= NN ? NN - 1 : s);
    d = d < 0 ? 0 : (d >= NN ? NN - 1 : d);
    g_src[i] = s; g_dst[i] = d;
    atomicAdd(&g_deg[d], 1);
    out_idx[i]      = (float)s;
    out_idx[EP + i] = (float)d;
}

// ---------------- one-block exclusive scan over degrees -> CSR offsets ----------
__global__ void __launch_bounds__(1024) k_scan() {
    __shared__ int part[1024];
    int tid = threadIdx.x;
    int base = tid * 10;
    int mysum = 0;
    #pragma unroll
    for (int i = 0; i < 10; i++) { int idx = base + i; if (idx < NN) mysum += g_deg[idx]; }
    part[tid] = mysum;
    __syncthreads();
    for (int off = 1; off < 1024; off <<= 1) {
        int v = (tid >= off) ? part[tid - off] : 0;
        __syncthreads();
        part[tid] += v;
        __syncthreads();
    }
    int run = part[tid] - mysum;   // exclusive start of my segment
    #pragma unroll
    for (int i = 0; i < 10; i++) {
        int idx = base + i;
        if (idx < NN) { g_off[idx] = run; g_cur[idx] = run; run += g_deg[idx]; }
    }
    if (tid == 1023) g_off[NN] = part[1023];
}

__global__ void k_scatter() {
    int e = blockIdx.x * blockDim.x + threadIdx.x;
    if (e >= EP) return;
    int d = g_dst[e];
    int pos = atomicAdd(&g_cur[d], 1);
    g_ce[pos] = e;
}

// ---------------- layer0 GEMM for ALL timesteps: xw0 = x @ W0 + a-reductions ----
// rows r = n*TT + t (x rows are contiguous in that order); 4 rows per 256-block
__global__ void __launch_bounds__(256) k_gemm0(
    const float* __restrict__ x, const float* __restrict__ W0,
    const float* __restrict__ a_src0, const float* __restrict__ a_dst0)
{
    int j = threadIdx.x & 63;
    int g = threadIdx.x >> 6;
    float wcol[FF];
    #pragma unroll
    for (int k = 0; k < FF; k++) wcol[k] = W0[k*HH + j];
    float asv = a_src0[j];
    float adv = a_dst0[j];
    int h = j >> 4;
    int r = blockIdx.x*4 + g;
    if (r >= NN*TT) return;
    int n = r / TT, t = r - n*TT;
    const float* xr = x + (size_t)r * FF;
    float acc = 0.0f;
    #pragma unroll
    for (int k = 0; k < FF; k++) acc += xr[k] * wcol[k];
    g_xw0[t*NN*HH + n*HH + j] = acc;
    float ps = acc * asv, pd = acc * adv;
    #pragma unroll
    for (int off = 8; off > 0; off >>= 1) {
        ps += __shfl_down_sync(0xffffffffu, ps, off, 16);
        pd += __shfl_down_sync(0xffffffffu, pd, off, 16);
    }
    if ((j & 15) == 0) {
        g_ssrc0[t*NN*NH + n*NH + h] = ps;
        g_sdst0[t*NN*NH + n*NH + h] = pd;
    }
}

// ---------------- per-edge exp(leakyrelu(logit)) for all t; layer selected on device ----
// (device symbols resolved IN device code — passing them from host is invalid)
__global__ void k_ex(int layer) {
    const float* __restrict__ ssrc = layer ? g_ssrc1 : g_ssrc0;
    const float* __restrict__ sdst = layer ? g_sdst1 : g_sdst0;
    float* __restrict__ exo        = layer ? g_ex1   : g_ex0;
    int i = blockIdx.x * blockDim.x + threadIdx.x;
    if (i >= TT*EP) return;
    int t = i / EP, e = i - t*EP;
    int s = g_src[e], d = g_dst[e];
    const float4 vs = *(const float4*)&ssrc[t*NN*NH + s*NH];
    const float4 vd = *(const float4*)&sdst[t*NN*NH + d*NH];
    float4 r;
    float a;
    a = vs.x + vd.x; a = a > 0.f ? a : 0.2f*a; r.x = __expf(a);
    a = vs.y + vd.y; a = a > 0.f ? a : 0.2f*a; r.y = __expf(a);
    a = vs.z + vd.z; a = a > 0.f ? a : 0.2f*a; r.z = __expf(a);
    a = vs.w + vd.w; a = a > 0.f ? a : 0.2f*a; r.w = __expf(a);
    *(float4*)&exo[t*EP*NH + e*NH] = r;
}

// ---------------- layer0 gather: per-dst softmax-weighted sum (no atomics) -----
// block = 256 = 4 (t,d) groups x 64 channels; grid covers TT*NN/4
__global__ void __launch_bounds__(256) k_gat0(const float* __restrict__ b0) {
    int id = blockIdx.x*4 + (threadIdx.x >> 6);
    if (id >= TT*NN) return;
    int t = id / NN, d = id - t*NN;
    int c = threadIdx.x & 63;
    int h = c >> 4;
    const float* ex0 = g_ex0 + t*EP*NH;
    const float* xw0 = g_xw0 + t*NN*HH;
    int kb = g_off[d], ke = g_off[d+1];
    float acc = 0.0f, sum = 0.0f;
    for (int k = kb; k < ke; k++) {
        int eid = g_ce[k];
        int s = g_src[eid];
        float ex = ex0[eid*NH + h];
        acc += ex * xw0[s*HH + c];
        sum += ex;
    }
    float v = acc / (sum + 1e-16f) + b0[c];
    g_h[t*NN*HH + d*HH + c] = v > 0.0f ? v : (expf(v) - 1.0f);
}

// ---------------- layer1 GEMM for all t: xw1 = h @ W1 [64,256] + a-reductions --
__global__ void __launch_bounds__(256) k_gemm1(
    const float* __restrict__ W1,
    const float* __restrict__ a_src1, const float* __restrict__ a_dst1)
{
    int j = threadIdx.x;
    float wcol[HH];
    #pragma unroll
    for (int k = 0; k < HH; k++) wcol[k] = W1[k*G1 + j];
    float asv = a_src1[j];
    float adv = a_dst1[j];
    __shared__ float sh_h[HH];
    __shared__ float sred[16];
    int warp = j >> 5, lane = j & 31;
    for (int id = blockIdx.x; id < TT*NN; id += gridDim.x) {
        if (j < HH) sh_h[j] = g_h[id*HH + j];   // id = t*NN+n, g_h is planar [t][n][64]
        __syncthreads();
        float acc = 0.0f;
        #pragma unroll
        for (int k = 0; k < HH; k++) acc += sh_h[k] * wcol[k];
        g_xw1[(size_t)id*G1 + j] = acc;
        float ps = acc * asv, pd = acc * adv;
        #pragma unroll
        for (int off = 16; off > 0; off >>= 1) {
            ps += __shfl_down_sync(0xffffffffu, ps, off);
            pd += __shfl_down_sync(0xffffffffu, pd, off);
        }
        if (lane == 0) { sred[warp] = ps; sred[8 + warp] = pd; }
        __syncthreads();
        if (j < NH) {
            g_ssrc1[id*NH + j] = sred[2*j] + sred[2*j + 1];
            g_sdst1[id*NH + j] = sred[8 + 2*j] + sred[8 + 2*j + 1];
        }
        __syncthreads();
    }
}

// ---------------- layer1 gather + head-mean + bias + elu + LayerNorm (fused) ---
// block = 256 per (t,d); j -> (h=j>>6, c=j&63)
__global__ void __launch_bounds__(256) k_gat1(
    const float* __restrict__ b1, const float* __restrict__ ln_g, const float* __restrict__ ln_b)
{
    int id = blockIdx.x;                 // t*NN + d
    int t = id / NN, d = id - t*NN;
    int j = threadIdx.x;
    int h = j >> 6, c = j & 63;
    const float* ex1 = g_ex1 + (size_t)t*EP*NH;
    const float* xw1 = g_xw1 + (size_t)t*NN*G1;
    int kb = g_off[d], ke = g_off[d+1];
    float acc = 0.0f, sum = 0.0f;
    for (int k = kb; k < ke; k++) {
        int eid = g_ce[k];
        int s = g_src[eid];
        float ex = ex1[eid*NH + h];
        acc += ex * xw1[(size_t)s*G1 + j];
        sum += ex;
    }
    if (t == TT-1 && c == 0) g_ssum1[d*NH + h] = sum;  // for alpha output

    __shared__ float sv[256];
    __shared__ float red[4];
    sv[j] = acc / (sum + 1e-16f);
    __syncthreads();

    float v = 0.0f;
    if (j < HH) {
        v = 0.25f*(sv[c] + sv[64 + c] + sv[128 + c] + sv[192 + c]) + b1[c];
        v = v > 0.0f ? v : (expf(v) - 1.0f);
        float s1 = v, s2 = v*v;
        #pragma unroll
        for (int off = 16; off > 0; off >>= 1) {
            s1 += __shfl_down_sync(0xffffffffu, s1, off);
            s2 += __shfl_down_sync(0xffffffffu, s2, off);
        }
        int w = j >> 5;
        if ((j & 31) == 0) { red[w] = s1; red[2 + w] = s2; }
    }
    __syncthreads();
    if (j < HH) {
        float mu  = (red[0] + red[1]) * (1.0f/64.0f);
        float var = (red[2] + red[3]) * (1.0f/64.0f) - mu*mu;
        float o = (v - mu) * rsqrtf(var + 1e-5f) * ln_g[c] + ln_b[c];
        g_Ht[(size_t)id*HH + c] = o;
    }
}

// ---------------- fused GRU step: gi/gh GEMVs + gate combine ----------------
__global__ void __launch_bounds__(192) k_grustep(
    const float* __restrict__ W_ih, const float* __restrict__ W_hh,
    const float* __restrict__ b_ih, const float* __restrict__ b_hh, int t)
{
    int j = threadIdx.x;   // 0..191
    float wih[HH], whh[HH];
    #pragma unroll
    for (int k = 0; k < HH; k++) { wih[k] = W_ih[j*HH + k]; whh[k] = W_hh[j*HH + k]; }
    float bi = b_ih[j], bh = b_hh[j];
    __shared__ float shx[HH], shh[HH], sgi[192], sgh[192];
    const float* Ht = g_Ht + (size_t)t*NN*HH;
    for (int n = blockIdx.x; n < NN; n += gridDim.x) {
        if (j < HH) { shx[j] = Ht[n*HH + j]; shh[j] = g_hgru[n*HH + j]; }
        __syncthreads();
        float gi = bi, gh = bh;
        #pragma unroll
        for (int k = 0; k < HH; k++) { gi += wih[k]*shx[k]; gh += whh[k]*shh[k]; }
        sgi[j] = gi; sgh[j] = gh;
        __syncthreads();
        if (j < HH) {
            float r = 1.0f / (1.0f + expf(-(sgi[j]        + sgh[j])));
            float z = 1.0f / (1.0f + expf(-(sgi[64 + j]   + sgh[64 + j])));
            float g = tanhf(sgi[128 + j] + r * sgh[128 + j]);
            g_hgru[n*HH + j] = (1.0f - z)*g + z*shh[j];
        }
        __syncthreads();
    }
}

// ---------------- alpha output (last timestep, layer1) ----------------
__global__ void k_alpha(float* __restrict__ out_alpha) {
    int i = blockIdx.x * blockDim.x + threadIdx.x;
    if (i >= EP*NH) return;
    int e = i >> 2, h = i & 3;
    int d = g_dst[e];
    out_alpha[i] = g_ex1[(size_t)(TT-1)*EP*NH + i] / (g_ssum1[d*NH + h] + 1e-16f);
}

__global__ void k_copy_h(float* __restrict__ out_h) {
    int i = blockIdx.x * blockDim.x + threadIdx.x;
    if (i < NN*HH) out_h[i] = g_hgru[i];
}

// ---------------- launch ----------------
extern "C" void kernel_launch(void* const* d_in, const int* in_sizes, int n_in,
                              void* d_out, int out_size) {
    const float* x       = (const float*)d_in[0];
    const void*  ei      = d_in[1];
    const float* W0      = (const float*)d_in[2];
    const float* a_src0  = (const float*)d_in[3];
    const float* a_dst0  = (const float*)d_in[4];
    const float* b0      = (const float*)d_in[5];
    const float* W1      = (const float*)d_in[6];
    const float* a_src1  = (const float*)d_in[7];
    const float* a_dst1  = (const float*)d_in[8];
    const float* b1      = (const float*)d_in[9];
    const float* ln_g    = (const float*)d_in[10];
    const float* ln_b    = (const float*)d_in[11];
    const float* W_ih    = (const float*)d_in[12];
    const float* W_hh    = (const float*)d_in[13];
    const float* b_ih    = (const float*)d_in[14];
    const float* b_hh    = (const float*)d_in[15];

    float* out       = (float*)d_out;
    float* out_h     = out;                        // [N*HID]
    float* out_alpha = out + NN*HH;                // [EP*NH]
    float* out_idx   = out + NN*HH + EP*NH;        // [2*EP]

    // graph prep + CSR build (once per launch)
    k_detect<<<1, 256>>>((const int*)ei);
    k_zerodeg<<<(NN*HH + 255)/256, 256>>>();
    k_prep<<<(EP + 255)/256, 256>>>(ei, out_idx);
    k_scan<<<1, 1024>>>();
    k_scatter<<<(EP + 255)/256, 256>>>();

    // GAT stack, batched over all timesteps
    k_gemm0<<<(NN*TT + 3)/4, 256>>>(x, W0, a_src0, a_dst0);
    k_ex<<<(TT*EP + 255)/256, 256>>>(0);
    k_gat0<<<(TT*NN + 3)/4, 256>>>(b0);
    k_gemm1<<<3750, 256>>>(W1, a_src1, a_dst1);
    k_ex<<<(TT*EP + 255)/256, 256>>>(1);
    k_gat1<<<TT*NN, 256>>>(b1, ln_g, ln_b);

    // sequential GRU
    for (int t = 0; t < TT; t++)
        k_grustep<<<500, 192>>>(W_ih, W_hh, b_ih, b_hh, t);

    k_alpha<<<(EP*NH + 255)/256, 256>>>(out_alpha);
    k_copy_h<<<(NN*HH + 255)/256, 256>>>(out_h);
}